// round 13
// baseline (speedup 1.0000x reference)
#include <cuda_runtime.h>
#include <cuda_bf16.h>
#include <cstdint>
#include <cstddef>
#include <math.h>

#define BATCH  256
#define HCLK   200
#define NCAND  64
#define DMODEL 640
#define NHEADS 10
#define HDIM   64
#define MROWS_K (BATCH*HCLK)
#define MROWS_Q (BATCH*NCAND)

// ---- scratch ----
__device__ __nv_bfloat16 g_Anb[(size_t)MROWS_K*DMODEL];
__device__ __nv_bfloat16 g_Atb[(size_t)MROWS_K*256];
__device__ __nv_bfloat16 g_Acb[(size_t)MROWS_Q*256];
__device__ __nv_bfloat16 g_Wkb[DMODEL*256];
__device__ __nv_bfloat16 g_Wqb[DMODEL*256];
__device__ __nv_bfloat16 g_Wgb[DMODEL*DMODEL];
__device__ __nv_bfloat16 g_Qbf[(size_t)MROWS_Q*DMODEL];
__device__ __nv_bfloat16 g_Kbf[(size_t)MROWS_K*DMODEL];
__device__ __nv_bfloat16 g_X  [(size_t)MROWS_K*DMODEL];
__device__ float         g_qw [MROWS_Q];
__device__ float         g_aggp[(size_t)BATCH*NHEADS*HCLK];
__device__ float         g_aw [MROWS_K];

#define MMA_BF16(d, a, b) \
  asm volatile( \
    "mma.sync.aligned.m16n8k16.row.col.f32.bf16.bf16.f32 " \
    "{%0,%1,%2,%3}, {%4,%5,%6,%7}, {%8,%9}, {%0,%1,%2,%3};\n" \
    : "+f"((d)[0]), "+f"((d)[1]), "+f"((d)[2]), "+f"((d)[3]) \
    : "r"((a)[0]), "r"((a)[1]), "r"((a)[2]), "r"((a)[3]), \
      "r"((b)[0]), "r"((b)[1]))

#define LDSM_X4(r0, r1, r2, r3, saddr) \
  asm volatile("ldmatrix.sync.aligned.m8n8.x4.shared.b16 {%0,%1,%2,%3}, [%4];\n" \
    : "=r"(r0), "=r"(r1), "=r"(r2), "=r"(r3) : "r"(saddr))

#define CP16(dst, src) do { \
    uint32_t _d = (uint32_t)__cvta_generic_to_shared(dst); \
    asm volatile("cp.async.cg.shared.global [%0], [%1], 16;\n" :: "r"(_d), "l"(src)); \
  } while (0)

// ---- single fused fp32 -> bf16 convert for all six tensors ----
__global__ __launch_bounds__(256)
void conv_all_kernel(const float* __restrict__ a0, __nv_bfloat16* __restrict__ o0, int n0,
                     const float* __restrict__ a1, __nv_bfloat16* __restrict__ o1, int n1,
                     const float* __restrict__ a2, __nv_bfloat16* __restrict__ o2, int n2,
                     const float* __restrict__ a3, __nv_bfloat16* __restrict__ o3, int n3,
                     const float* __restrict__ a4, __nv_bfloat16* __restrict__ o4, int n4,
                     const float* __restrict__ a5, __nv_bfloat16* __restrict__ o5, int n5)
{
    const int stride = gridDim.x*256*4;
    const int t0 = (blockIdx.x*256 + threadIdx.x)*4;
    #define CONV_LOOP(a, o, n) \
        for (int i = t0; i < (n); i += stride) { \
            float4 v = *(const float4*)((a) + i); \
            *(__nv_bfloat162*)((o) + i)     = __floats2bfloat162_rn(v.x, v.y); \
            *(__nv_bfloat162*)((o) + i + 2) = __floats2bfloat162_rn(v.z, v.w); \
        }
    CONV_LOOP(a0, o0, n0)
    CONV_LOOP(a1, o1, n1)
    CONV_LOOP(a2, o2, n2)
    CONV_LOOP(a3, o3, n3)
    CONV_LOOP(a4, o4, n4)
    CONV_LOOP(a5, o5, n5)
    #undef CONV_LOOP
}

// ---- bf16 GEMM v3: 3-stage cp.async ring, one sync per slab, persistent CTAs ----
#define SST 72
#define TSTAGE (256*SST)                 // elements per stage (As 128 rows + Bs 128 rows)
#define NSTAGE 3
#define GEMM_SMEM (NSTAGE*TSTAGE*2)      // 110592 bytes
#define NTN 5                            // N tiles (640/128)
template<bool BIAS>
__global__ __launch_bounds__(256)
void gemm_bf16(const __nv_bfloat16* __restrict__ A, const __nv_bfloat16* __restrict__ W,
               const float* __restrict__ bias, __nv_bfloat16* __restrict__ C,
               int K, int ntiles)
{
    extern __shared__ __nv_bfloat16 sh[];
    const int tid = threadIdx.x;
    const int warp = tid >> 5, lane = tid & 31;
    const int wm = warp & 3, wn = warp >> 2;
    const int g = lane >> 2, tig = lane & 3;

    const int a_r = lane & 15;
    const int a_c = (lane >> 4) << 3;
    const int b_r = ((lane >> 4) << 3) + (lane & 7);
    const int b_c = ((lane >> 3) & 1) << 3;

    const int nk = K / 64;

    for (int t = blockIdx.x; t < ntiles; t += gridDim.x) {
        const int bn0 = (t % NTN)*128;
        const int bm0 = (t / NTN)*128;

        float acc[2][8][4];
        #pragma unroll
        for (int i = 0; i < 2; i++)
          #pragma unroll
          for (int j = 0; j < 8; j++)
            #pragma unroll
            for (int v = 0; v < 4; v++) acc[i][j][v] = 0.f;

        auto issue = [&](int kb, int s) {
            const int k0 = kb * 64;
            __nv_bfloat16* As = sh + s*TSTAGE;
            __nv_bfloat16* Bs = As + 128*SST;
            #pragma unroll
            for (int it = 0; it < 4; it++) {
                int idx = tid + it*256;
                int r = idx >> 3, c8 = (idx & 7) << 3;
                CP16(&As[r*SST + c8], &A[(size_t)(bm0 + r)*K + k0 + c8]);
                CP16(&Bs[r*SST + c8], &W[(size_t)(bn0 + r)*K + k0 + c8]);
            }
            asm volatile("cp.async.commit_group;\n");
        };

        // prologue: 2 stages in flight
        issue(0, 0);
        issue(1, 1);

        for (int kb = 0; kb < nk; kb++) {
            if (kb + 1 < nk) asm volatile("cp.async.wait_group 1;\n");
            else             asm volatile("cp.async.wait_group 0;\n");
            __syncthreads();
            if (kb + 2 < nk) issue(kb + 2, (kb + 2) % NSTAGE);

            const __nv_bfloat16* As = sh + (kb % NSTAGE)*TSTAGE;
            const __nv_bfloat16* Bs = As + 128*SST;
            uint32_t As0 = (uint32_t)__cvta_generic_to_shared(As);
            uint32_t Bs0 = (uint32_t)__cvta_generic_to_shared(Bs);
            #pragma unroll
            for (int ks = 0; ks < 4; ks++) {
                const int kk = ks*16;
                uint32_t afr[2][4];
                #pragma unroll
                for (int i = 0; i < 2; i++) {
                    uint32_t ad = As0 + ((wm*32 + i*16 + a_r)*SST + kk + a_c)*2;
                    LDSM_X4(afr[i][0], afr[i][1], afr[i][2], afr[i][3], ad);
                }
                uint32_t bfr[4][4];
                #pragma unroll
                for (int j2 = 0; j2 < 4; j2++) {
                    uint32_t bd = Bs0 + ((wn*64 + j2*16 + b_r)*SST + kk + b_c)*2;
                    LDSM_X4(bfr[j2][0], bfr[j2][1], bfr[j2][2], bfr[j2][3], bd);
                }
                #pragma unroll
                for (int i = 0; i < 2; i++)
                  #pragma unroll
                  for (int j2 = 0; j2 < 4; j2++) {
                    MMA_BF16(acc[i][2*j2],   afr[i], (&bfr[j2][0]));
                    MMA_BF16(acc[i][2*j2+1], afr[i], (&bfr[j2][2]));
                  }
            }
        }

        #pragma unroll
        for (int i = 0; i < 2; i++) {
            int row = bm0 + wm*32 + i*16 + g;
            #pragma unroll
            for (int j = 0; j < 8; j++) {
                int col = bn0 + wn*64 + j*8 + 2*tig;
                float b0 = 0.f, b1 = 0.f;
                if (BIAS) { b0 = bias[col]; b1 = bias[col+1]; }
                *(__nv_bfloat162*)(&C[(size_t)row*DMODEL + col]) =
                    __floats2bfloat162_rn(acc[i][j][0] + b0, acc[i][j][1] + b1);
                *(__nv_bfloat162*)(&C[(size_t)(row+8)*DMODEL + col]) =
                    __floats2bfloat162_rn(acc[i][j][2] + b0, acc[i][j][3] + b1);
            }
        }
        __syncthreads();   // protect ring slots before next tile's prologue
    }
}

// ---- qw ----
__global__ __launch_bounds__(256)
void qw_kernel()
{
    __shared__ float sv[NCAND], se[NCAND];
    const int b = blockIdx.x, tid = threadIdx.x;
    const int warp = tid >> 5, lane = tid & 31;
    for (int n = warp; n < NCAND; n += 8) {
        const __nv_bfloat16* q = g_Qbf + (size_t)(b*NCAND + n)*DMODEL;
        float ssq = 0.f;
        #pragma unroll
        for (int i = 0; i < 5; i++) {
            int c = (lane + i*32)*4;
            __nv_bfloat162 x0 = *(const __nv_bfloat162*)(q + c);
            __nv_bfloat162 x1 = *(const __nv_bfloat162*)(q + c + 2);
            float a = __low2float(x0), d = __high2float(x0);
            float e = __low2float(x1), f = __high2float(x1);
            ssq += a*a + d*d + e*e + f*f;
        }
        #pragma unroll
        for (int o = 16; o; o >>= 1) ssq += __shfl_xor_sync(0xffffffffu, ssq, o);
        if (lane == 0) sv[n] = sqrtf(ssq);
    }
    __syncthreads();
    if (tid < NCAND) {
        float mx = -1e30f;
        for (int i = 0; i < NCAND; i++) mx = fmaxf(mx, sv[i]);
        se[tid] = __expf(sv[tid] - mx);
    }
    __syncthreads();
    if (tid < NCAND) {
        float s = 0.f;
        for (int i = 0; i < NCAND; i++) s += se[i];
        g_qw[b*NCAND + tid] = se[tid] / s;
    }
}

// ---- attention per (b,h) ----
#define QSTR 72
#define SSTR 204
#define ATTN_SMEM ((64*QSTR + HCLK*QSTR)*2 + 64*SSTR*4)
__global__ __launch_bounds__(128)
void attn_kernel()
{
    extern __shared__ char sm[];
    __nv_bfloat16* Qs = (__nv_bfloat16*)sm;
    __nv_bfloat16* Ks = Qs + 64*QSTR;
    float* S = (float*)(sm + (64*QSTR + HCLK*QSTR)*2);
    __shared__ float coef[64];

    const int h = blockIdx.x, b = blockIdx.y;
    const int tid = threadIdx.x;
    const int warp = tid >> 5, lane = tid & 31;
    const int g = lane >> 2, tig = lane & 3;

    for (int idx = tid; idx < 64*8; idx += 128) {
        int n = idx >> 3, c = (idx & 7) << 3;
        *(uint4*)(&Qs[n*QSTR + c]) =
            *(const uint4*)(g_Qbf + (size_t)(b*NCAND + n)*DMODEL + h*HDIM + c);
    }
    for (int idx = tid; idx < HCLK*8; idx += 128) {
        int m = idx >> 3, c = (idx & 7) << 3;
        *(uint4*)(&Ks[m*QSTR + c]) =
            *(const uint4*)(g_Kbf + (size_t)(b*HCLK + m)*DMODEL + h*HDIM + c);
    }
    __syncthreads();

    uint32_t afr[4][4];
    #pragma unroll
    for (int kt = 0; kt < 4; kt++) {
        const __nv_bfloat16* p = &Qs[(warp*16 + g)*QSTR + kt*16 + 2*tig];
        afr[kt][0] = *(const uint32_t*)(p);
        afr[kt][1] = *(const uint32_t*)(p + 8*QSTR);
        afr[kt][2] = *(const uint32_t*)(p + 8);
        afr[kt][3] = *(const uint32_t*)(p + 8*QSTR + 8);
    }
    const float iscale = rsqrtf((float)DMODEL);
    for (int nt = 0; nt < 25; nt++) {
        float c4[4] = {0.f, 0.f, 0.f, 0.f};
        #pragma unroll
        for (int kt = 0; kt < 4; kt++) {
            uint32_t bfr[2];
            const __nv_bfloat16* p = &Ks[(nt*8 + g)*QSTR + kt*16 + 2*tig];
            bfr[0] = *(const uint32_t*)(p);
            bfr[1] = *(const uint32_t*)(p + 8);
            MMA_BF16(c4, afr[kt], bfr);
        }
        int r0 = warp*16 + g, c0 = nt*8 + 2*tig;
        S[r0*SSTR + c0]       = c4[0] * iscale;
        S[r0*SSTR + c0+1]     = c4[1] * iscale;
        S[(r0+8)*SSTR + c0]   = c4[2] * iscale;
        S[(r0+8)*SSTR + c0+1] = c4[3] * iscale;
    }
    __syncthreads();

    for (int n = warp; n < 64; n += 4) {
        float mx = -1e30f;
        for (int m = lane; m < HCLK; m += 32) mx = fmaxf(mx, S[n*SSTR + m]);
        #pragma unroll
        for (int o = 16; o; o >>= 1) mx = fmaxf(mx, __shfl_xor_sync(0xffffffffu, mx, o));
        float s = 0.f;
        for (int m = lane; m < HCLK; m += 32) {
            float e = __expf(S[n*SSTR + m] - mx);
            S[n*SSTR + m] = e;
            s += e;
        }
        #pragma unroll
        for (int o = 16; o; o >>= 1) s += __shfl_xor_sync(0xffffffffu, s, o);
        if (lane == 0) coef[n] = g_qw[b*NCAND + n] / s;
    }
    __syncthreads();

    for (int m = tid; m < HCLK; m += 128) {
        float a = 0.f;
        #pragma unroll 8
        for (int n = 0; n < 64; n++) a += coef[n] * S[n*SSTR + m];
        g_aggp[((size_t)b*NHEADS + h)*HCLK + m] = a;
    }
}

// ---- head-reduce + softmax -> aw ----
__global__ __launch_bounds__(256)
void aggsm_kernel(float* __restrict__ out_tail)
{
    __shared__ float sa[HCLK], se2[HCLK];
    const int b = blockIdx.x, t = threadIdx.x;
    if (t < HCLK) {
        float a = 0.f;
        #pragma unroll
        for (int h = 0; h < NHEADS; h++)
            a += g_aggp[((size_t)b*NHEADS + h)*HCLK + t];
        sa[t] = a;
    }
    __syncthreads();
    if (t < HCLK) {
        float mx = -1e30f;
        for (int i = 0; i < HCLK; i++) mx = fmaxf(mx, sa[i]);
        se2[t] = __expf(sa[t] - mx);
    }
    __syncthreads();
    if (t < HCLK) {
        float s = 0.f;
        for (int i = 0; i < HCLK; i++) s += se2[i];
        float aw = se2[t] / s;
        g_aw[b*HCLK + t] = aw;
        out_tail[b*HCLK + t] = aw;
    }
}

// ---- gate + residual + LayerNorm, float4-vectorized ----
__global__ __launch_bounds__(160)
void epilogue_kernel(const float* __restrict__ clicked, const float* __restrict__ bg,
                     const float* __restrict__ gamma, const float* __restrict__ beta,
                     float* __restrict__ out)
{
    const int row = blockIdx.x, tid = threadIdx.x;
    const float aw = g_aw[row];
    const float4 c4 = ((const float4*)(clicked + (size_t)row*DMODEL))[tid];
    const uint2 xu  = ((const uint2*)(g_X + (size_t)row*DMODEL))[tid];
    const float4 bg4 = ((const float4*)bg)[tid];
    __nv_bfloat162 x01 = *(const __nv_bfloat162*)&xu.x;
    __nv_bfloat162 x23 = *(const __nv_bfloat162*)&xu.y;
    float xs[4] = { __low2float(x01), __high2float(x01), __low2float(x23), __high2float(x23) };
    float cs[4] = { c4.x, c4.y, c4.z, c4.w };
    float bgs[4] = { bg4.x, bg4.y, bg4.z, bg4.w };
    float ov[4];
    float s = 0.f, sq = 0.f;
    #pragma unroll
    for (int i = 0; i < 4; i++) {
        float z = aw * xs[i] + bgs[i];
        float gate = 1.f / (1.f + __expf(-z));
        float o = gate * (aw * cs[i]) + (1.f - gate) * cs[i];
        ov[i] = o;
        s += o; sq += o*o;
    }
    __shared__ float rs[5], rq[5];
    #pragma unroll
    for (int off = 16; off > 0; off >>= 1) {
        s  += __shfl_xor_sync(0xffffffffu, s, off);
        sq += __shfl_xor_sync(0xffffffffu, sq, off);
    }
    if ((tid & 31) == 0) { rs[tid >> 5] = s; rq[tid >> 5] = sq; }
    __syncthreads();
    float ts = rs[0] + rs[1] + rs[2] + rs[3] + rs[4];
    float tq = rq[0] + rq[1] + rq[2] + rq[3] + rq[4];
    float mu = ts / DMODEL;
    float var = tq / DMODEL - mu*mu;
    float inv = rsqrtf(var + 1e-5f);
    const float4 gm4 = ((const float4*)gamma)[tid];
    const float4 bt4 = ((const float4*)beta)[tid];
    float gms[4] = { gm4.x, gm4.y, gm4.z, gm4.w };
    float bts[4] = { bt4.x, bt4.y, bt4.z, bt4.w };
    float4 o4;
    o4.x = (ov[0] - mu) * inv * gms[0] + bts[0];
    o4.y = (ov[1] - mu) * inv * gms[1] + bts[1];
    o4.z = (ov[2] - mu) * inv * gms[2] + bts[2];
    o4.w = (ov[3] - mu) * inv * gms[3] + bts[3];
    ((float4*)(out + (size_t)row*DMODEL))[tid] = o4;
}

extern "C" void kernel_launch(void* const* d_in, const int* in_sizes, int n_in,
                              void* d_out, int out_size)
{
    const float* clicked_news   = (const float*)d_in[0];
    const float* clicked_topics = (const float*)d_in[1];
    const float* cand_topics    = (const float*)d_in[2];
    const float* Wq = (const float*)d_in[3];
    const float* bq = (const float*)d_in[4];
    const float* Wk = (const float*)d_in[5];
    const float* bk = (const float*)d_in[6];
    const float* Wg = (const float*)d_in[9];
    const float* bg = (const float*)d_in[10];
    const float* ln_gamma = (const float*)d_in[11];
    const float* ln_beta  = (const float*)d_in[12];
    float* out = (float*)d_out;

    cudaFuncSetAttribute(gemm_bf16<true>,  cudaFuncAttributeMaxDynamicSharedMemorySize, GEMM_SMEM);
    cudaFuncSetAttribute(gemm_bf16<false>, cudaFuncAttributeMaxDynamicSharedMemorySize, GEMM_SMEM);
    cudaFuncSetAttribute(attn_kernel, cudaFuncAttributeMaxDynamicSharedMemorySize, ATTN_SMEM);

    __nv_bfloat16 *p_Anb, *p_Atb, *p_Acb, *p_Wkb, *p_Wqb, *p_Wgb, *p_Qbf, *p_Kbf, *p_X;
    cudaGetSymbolAddress((void**)&p_Anb, g_Anb);
    cudaGetSymbolAddress((void**)&p_Atb, g_Atb);
    cudaGetSymbolAddress((void**)&p_Acb, g_Acb);
    cudaGetSymbolAddress((void**)&p_Wkb, g_Wkb);
    cudaGetSymbolAddress((void**)&p_Wqb, g_Wqb);
    cudaGetSymbolAddress((void**)&p_Wgb, g_Wgb);
    cudaGetSymbolAddress((void**)&p_Qbf, g_Qbf);
    cudaGetSymbolAddress((void**)&p_Kbf, g_Kbf);
    cudaGetSymbolAddress((void**)&p_X,   g_X);

    int nsm = 148, occT = 1, occF = 1;
    cudaDeviceGetAttribute(&nsm, cudaDevAttrMultiProcessorCount, 0);
    cudaOccupancyMaxActiveBlocksPerMultiprocessor(&occT, gemm_bf16<true>,  256, GEMM_SMEM);
    cudaOccupancyMaxActiveBlocksPerMultiprocessor(&occF, gemm_bf16<false>, 256, GEMM_SMEM);
    if (occT < 1) occT = 1;
    if (occF < 1) occF = 1;
    const int ntK = NTN * (MROWS_K/128);   // 2000
    const int ntQ = NTN * (MROWS_Q/128);   // 640
    int gT = occT * nsm; if (gT > ntK) gT = ntK;
    int gQ = occT * nsm; if (gQ > ntQ) gQ = ntQ;
    int gF = occF * nsm; if (gF > ntK) gF = ntK;

    // launch order: conv(1), gemmQ(2), gemmK(3), gemmX(4 <- ncu capture), ...
    conv_all_kernel<<<2048, 256>>>(
        clicked_news,   p_Anb, MROWS_K*DMODEL,
        clicked_topics, p_Atb, MROWS_K*256,
        cand_topics,    p_Acb, MROWS_Q*256,
        Wk, p_Wkb, DMODEL*256,
        Wq, p_Wqb, DMODEL*256,
        Wg, p_Wgb, DMODEL*DMODEL);

    gemm_bf16<true><<<gQ, 256, GEMM_SMEM>>>(p_Acb, p_Wqb, bq, p_Qbf, 256, ntQ);
    gemm_bf16<true><<<gT, 256, GEMM_SMEM>>>(p_Atb, p_Wkb, bk, p_Kbf, 256, ntK);
    gemm_bf16<false><<<gF, 256, GEMM_SMEM>>>(p_Anb, p_Wgb, nullptr, p_X, DMODEL, ntK);
    qw_kernel<<<BATCH, 256>>>();
    attn_kernel<<<dim3(NHEADS, BATCH), 128, ATTN_SMEM>>>();
    aggsm_kernel<<<BATCH, 256>>>(out + (size_t)MROWS_K*DMODEL);
    epilogue_kernel<<<MROWS_K, 160>>>(clicked_news, bg, ln_gamma, ln_beta, out);
}

// round 14
// speedup vs baseline: 1.0033x; 1.0033x over previous
#include <cuda_runtime.h>
#include <cuda_bf16.h>
#include <cstdint>
#include <cstddef>
#include <math.h>

#define BATCH  256
#define HCLK   200
#define NCAND  64
#define DMODEL 640
#define NHEADS 10
#define HDIM   64
#define MROWS_K (BATCH*HCLK)
#define MROWS_Q (BATCH*NCAND)

// ---- scratch ----
__device__ __nv_bfloat16 g_Anb[(size_t)MROWS_K*DMODEL];
__device__ __nv_bfloat16 g_Atb[(size_t)MROWS_K*256];
__device__ __nv_bfloat16 g_Acb[(size_t)MROWS_Q*256];
__device__ __nv_bfloat16 g_Wkb[DMODEL*256];
__device__ __nv_bfloat16 g_Wqb[DMODEL*256];
__device__ __nv_bfloat16 g_Wgb[DMODEL*DMODEL];
__device__ __nv_bfloat16 g_Qbf[(size_t)MROWS_Q*DMODEL];
__device__ __nv_bfloat16 g_Kbf[(size_t)MROWS_K*DMODEL];
__device__ __nv_bfloat16 g_X  [(size_t)MROWS_K*DMODEL];
__device__ float         g_qw [MROWS_Q];
__device__ float         g_aggp[(size_t)BATCH*NHEADS*HCLK];
__device__ float         g_aw [MROWS_K];

#define MMA_BF16(d, a, b) \
  asm volatile( \
    "mma.sync.aligned.m16n8k16.row.col.f32.bf16.bf16.f32 " \
    "{%0,%1,%2,%3}, {%4,%5,%6,%7}, {%8,%9}, {%0,%1,%2,%3};\n" \
    : "+f"((d)[0]), "+f"((d)[1]), "+f"((d)[2]), "+f"((d)[3]) \
    : "r"((a)[0]), "r"((a)[1]), "r"((a)[2]), "r"((a)[3]), \
      "r"((b)[0]), "r"((b)[1]))

#define LDSM_X4(r0, r1, r2, r3, saddr) \
  asm volatile("ldmatrix.sync.aligned.m8n8.x4.shared.b16 {%0,%1,%2,%3}, [%4];\n" \
    : "=r"(r0), "=r"(r1), "=r"(r2), "=r"(r3) : "r"(saddr))

#define CP16(dst, src) do { \
    uint32_t _d = (uint32_t)__cvta_generic_to_shared(dst); \
    asm volatile("cp.async.cg.shared.global [%0], [%1], 16;\n" :: "r"(_d), "l"(src)); \
  } while (0)

// ---- single fused fp32 -> bf16 convert for all six tensors ----
__global__ __launch_bounds__(256)
void conv_all_kernel(const float* __restrict__ a0, __nv_bfloat16* __restrict__ o0, int n0,
                     const float* __restrict__ a1, __nv_bfloat16* __restrict__ o1, int n1,
                     const float* __restrict__ a2, __nv_bfloat16* __restrict__ o2, int n2,
                     const float* __restrict__ a3, __nv_bfloat16* __restrict__ o3, int n3,
                     const float* __restrict__ a4, __nv_bfloat16* __restrict__ o4, int n4,
                     const float* __restrict__ a5, __nv_bfloat16* __restrict__ o5, int n5)
{
    const int stride = gridDim.x*256*4;
    const int t0 = (blockIdx.x*256 + threadIdx.x)*4;
    #define CONV_LOOP(a, o, n) \
        for (int i = t0; i < (n); i += stride) { \
            float4 v = *(const float4*)((a) + i); \
            *(__nv_bfloat162*)((o) + i)     = __floats2bfloat162_rn(v.x, v.y); \
            *(__nv_bfloat162*)((o) + i + 2) = __floats2bfloat162_rn(v.z, v.w); \
        }
    CONV_LOOP(a0, o0, n0)
    CONV_LOOP(a1, o1, n1)
    CONV_LOOP(a2, o2, n2)
    CONV_LOOP(a3, o3, n3)
    CONV_LOOP(a4, o4, n4)
    CONV_LOOP(a5, o5, n5)
    #undef CONV_LOOP
}

// ---- bf16 GEMM v3: 3-stage cp.async ring, one sync per slab, persistent CTAs ----
#define SST 72
#define TSTAGE (256*SST)                 // elements per stage (As 128 rows + Bs 128 rows)
#define NSTAGE 3
#define GEMM_SMEM (NSTAGE*TSTAGE*2)      // 110592 bytes
#define NTN 5                            // N tiles (640/128)
template<bool BIAS>
__global__ __launch_bounds__(256)
void gemm_bf16(const __nv_bfloat16* __restrict__ A, const __nv_bfloat16* __restrict__ W,
               const float* __restrict__ bias, __nv_bfloat16* __restrict__ C,
               int K, int ntiles)
{
    extern __shared__ __nv_bfloat16 sh[];
    const int tid = threadIdx.x;
    const int warp = tid >> 5, lane = tid & 31;
    const int wm = warp & 3, wn = warp >> 2;
    const int g = lane >> 2, tig = lane & 3;

    const int a_r = lane & 15;
    const int a_c = (lane >> 4) << 3;
    const int b_r = ((lane >> 4) << 3) + (lane & 7);
    const int b_c = ((lane >> 3) & 1) << 3;

    const int nk = K / 64;

    for (int t = blockIdx.x; t < ntiles; t += gridDim.x) {
        const int bn0 = (t % NTN)*128;
        const int bm0 = (t / NTN)*128;

        float acc[2][8][4];
        #pragma unroll
        for (int i = 0; i < 2; i++)
          #pragma unroll
          for (int j = 0; j < 8; j++)
            #pragma unroll
            for (int v = 0; v < 4; v++) acc[i][j][v] = 0.f;

        auto issue = [&](int kb, int s) {
            const int k0 = kb * 64;
            __nv_bfloat16* As = sh + s*TSTAGE;
            __nv_bfloat16* Bs = As + 128*SST;
            #pragma unroll
            for (int it = 0; it < 4; it++) {
                int idx = tid + it*256;
                int r = idx >> 3, c8 = (idx & 7) << 3;
                CP16(&As[r*SST + c8], &A[(size_t)(bm0 + r)*K + k0 + c8]);
                CP16(&Bs[r*SST + c8], &W[(size_t)(bn0 + r)*K + k0 + c8]);
            }
            asm volatile("cp.async.commit_group;\n");
        };

        // prologue: 2 stages in flight
        issue(0, 0);
        issue(1, 1);

        for (int kb = 0; kb < nk; kb++) {
            if (kb + 1 < nk) asm volatile("cp.async.wait_group 1;\n");
            else             asm volatile("cp.async.wait_group 0;\n");
            __syncthreads();
            if (kb + 2 < nk) issue(kb + 2, (kb + 2) % NSTAGE);

            const __nv_bfloat16* As = sh + (kb % NSTAGE)*TSTAGE;
            const __nv_bfloat16* Bs = As + 128*SST;
            uint32_t As0 = (uint32_t)__cvta_generic_to_shared(As);
            uint32_t Bs0 = (uint32_t)__cvta_generic_to_shared(Bs);
            #pragma unroll
            for (int ks = 0; ks < 4; ks++) {
                const int kk = ks*16;
                uint32_t afr[2][4];
                #pragma unroll
                for (int i = 0; i < 2; i++) {
                    uint32_t ad = As0 + ((wm*32 + i*16 + a_r)*SST + kk + a_c)*2;
                    LDSM_X4(afr[i][0], afr[i][1], afr[i][2], afr[i][3], ad);
                }
                uint32_t bfr[4][4];
                #pragma unroll
                for (int j2 = 0; j2 < 4; j2++) {
                    uint32_t bd = Bs0 + ((wn*64 + j2*16 + b_r)*SST + kk + b_c)*2;
                    LDSM_X4(bfr[j2][0], bfr[j2][1], bfr[j2][2], bfr[j2][3], bd);
                }
                #pragma unroll
                for (int i = 0; i < 2; i++)
                  #pragma unroll
                  for (int j2 = 0; j2 < 4; j2++) {
                    MMA_BF16(acc[i][2*j2],   afr[i], (&bfr[j2][0]));
                    MMA_BF16(acc[i][2*j2+1], afr[i], (&bfr[j2][2]));
                  }
            }
        }

        #pragma unroll
        for (int i = 0; i < 2; i++) {
            int row = bm0 + wm*32 + i*16 + g;
            #pragma unroll
            for (int j = 0; j < 8; j++) {
                int col = bn0 + wn*64 + j*8 + 2*tig;
                float b0 = 0.f, b1 = 0.f;
                if (BIAS) { b0 = bias[col]; b1 = bias[col+1]; }
                *(__nv_bfloat162*)(&C[(size_t)row*DMODEL + col]) =
                    __floats2bfloat162_rn(acc[i][j][0] + b0, acc[i][j][1] + b1);
                *(__nv_bfloat162*)(&C[(size_t)(row+8)*DMODEL + col]) =
                    __floats2bfloat162_rn(acc[i][j][2] + b0, acc[i][j][3] + b1);
            }
        }
        __syncthreads();   // protect ring slots before next tile's prologue
    }
}

// ---- qw ----
__global__ __launch_bounds__(256)
void qw_kernel()
{
    __shared__ float sv[NCAND], se[NCAND];
    const int b = blockIdx.x, tid = threadIdx.x;
    const int warp = tid >> 5, lane = tid & 31;
    for (int n = warp; n < NCAND; n += 8) {
        const __nv_bfloat16* q = g_Qbf + (size_t)(b*NCAND + n)*DMODEL;
        float ssq = 0.f;
        #pragma unroll
        for (int i = 0; i < 5; i++) {
            int c = (lane + i*32)*4;
            __nv_bfloat162 x0 = *(const __nv_bfloat162*)(q + c);
            __nv_bfloat162 x1 = *(const __nv_bfloat162*)(q + c + 2);
            float a = __low2float(x0), d = __high2float(x0);
            float e = __low2float(x1), f = __high2float(x1);
            ssq += a*a + d*d + e*e + f*f;
        }
        #pragma unroll
        for (int o = 16; o; o >>= 1) ssq += __shfl_xor_sync(0xffffffffu, ssq, o);
        if (lane == 0) sv[n] = sqrtf(ssq);
    }
    __syncthreads();
    if (tid < NCAND) {
        float mx = -1e30f;
        for (int i = 0; i < NCAND; i++) mx = fmaxf(mx, sv[i]);
        se[tid] = __expf(sv[tid] - mx);
    }
    __syncthreads();
    if (tid < NCAND) {
        float s = 0.f;
        for (int i = 0; i < NCAND; i++) s += se[i];
        g_qw[b*NCAND + tid] = se[tid] / s;
    }
}

// ---- attention per (b,h) ----
#define QSTR 72
#define SSTR 204
#define ATTN_SMEM ((64*QSTR + HCLK*QSTR)*2 + 64*SSTR*4)
__global__ __launch_bounds__(128)
void attn_kernel()
{
    extern __shared__ char sm[];
    __nv_bfloat16* Qs = (__nv_bfloat16*)sm;
    __nv_bfloat16* Ks = Qs + 64*QSTR;
    float* S = (float*)(sm + (64*QSTR + HCLK*QSTR)*2);
    __shared__ float coef[64];

    const int h = blockIdx.x, b = blockIdx.y;
    const int tid = threadIdx.x;
    const int warp = tid >> 5, lane = tid & 31;
    const int g = lane >> 2, tig = lane & 3;

    for (int idx = tid; idx < 64*8; idx += 128) {
        int n = idx >> 3, c = (idx & 7) << 3;
        *(uint4*)(&Qs[n*QSTR + c]) =
            *(const uint4*)(g_Qbf + (size_t)(b*NCAND + n)*DMODEL + h*HDIM + c);
    }
    for (int idx = tid; idx < HCLK*8; idx += 128) {
        int m = idx >> 3, c = (idx & 7) << 3;
        *(uint4*)(&Ks[m*QSTR + c]) =
            *(const uint4*)(g_Kbf + (size_t)(b*HCLK + m)*DMODEL + h*HDIM + c);
    }
    __syncthreads();

    uint32_t afr[4][4];
    #pragma unroll
    for (int kt = 0; kt < 4; kt++) {
        const __nv_bfloat16* p = &Qs[(warp*16 + g)*QSTR + kt*16 + 2*tig];
        afr[kt][0] = *(const uint32_t*)(p);
        afr[kt][1] = *(const uint32_t*)(p + 8*QSTR);
        afr[kt][2] = *(const uint32_t*)(p + 8);
        afr[kt][3] = *(const uint32_t*)(p + 8*QSTR + 8);
    }
    const float iscale = rsqrtf((float)DMODEL);
    for (int nt = 0; nt < 25; nt++) {
        float c4[4] = {0.f, 0.f, 0.f, 0.f};
        #pragma unroll
        for (int kt = 0; kt < 4; kt++) {
            uint32_t bfr[2];
            const __nv_bfloat16* p = &Ks[(nt*8 + g)*QSTR + kt*16 + 2*tig];
            bfr[0] = *(const uint32_t*)(p);
            bfr[1] = *(const uint32_t*)(p + 8);
            MMA_BF16(c4, afr[kt], bfr);
        }
        int r0 = warp*16 + g, c0 = nt*8 + 2*tig;
        S[r0*SSTR + c0]       = c4[0] * iscale;
        S[r0*SSTR + c0+1]     = c4[1] * iscale;
        S[(r0+8)*SSTR + c0]   = c4[2] * iscale;
        S[(r0+8)*SSTR + c0+1] = c4[3] * iscale;
    }
    __syncthreads();

    for (int n = warp; n < 64; n += 4) {
        float mx = -1e30f;
        for (int m = lane; m < HCLK; m += 32) mx = fmaxf(mx, S[n*SSTR + m]);
        #pragma unroll
        for (int o = 16; o; o >>= 1) mx = fmaxf(mx, __shfl_xor_sync(0xffffffffu, mx, o));
        float s = 0.f;
        for (int m = lane; m < HCLK; m += 32) {
            float e = __expf(S[n*SSTR + m] - mx);
            S[n*SSTR + m] = e;
            s += e;
        }
        #pragma unroll
        for (int o = 16; o; o >>= 1) s += __shfl_xor_sync(0xffffffffu, s, o);
        if (lane == 0) coef[n] = g_qw[b*NCAND + n] / s;
    }
    __syncthreads();

    for (int m = tid; m < HCLK; m += 128) {
        float a = 0.f;
        #pragma unroll 8
        for (int n = 0; n < 64; n++) a += coef[n] * S[n*SSTR + m];
        g_aggp[((size_t)b*NHEADS + h)*HCLK + m] = a;
    }
}

// ---- head-reduce + softmax -> aw ----
__global__ __launch_bounds__(256)
void aggsm_kernel(float* __restrict__ out_tail)
{
    __shared__ float sa[HCLK], se2[HCLK];
    const int b = blockIdx.x, t = threadIdx.x;
    if (t < HCLK) {
        float a = 0.f;
        #pragma unroll
        for (int h = 0; h < NHEADS; h++)
            a += g_aggp[((size_t)b*NHEADS + h)*HCLK + t];
        sa[t] = a;
    }
    __syncthreads();
    if (t < HCLK) {
        float mx = -1e30f;
        for (int i = 0; i < HCLK; i++) mx = fmaxf(mx, sa[i]);
        se2[t] = __expf(sa[t] - mx);
    }
    __syncthreads();
    if (t < HCLK) {
        float s = 0.f;
        for (int i = 0; i < HCLK; i++) s += se2[i];
        float aw = se2[t] / s;
        g_aw[b*HCLK + t] = aw;
        out_tail[b*HCLK + t] = aw;
    }
}

// ---- gate + residual + LayerNorm, float4-vectorized ----
__global__ __launch_bounds__(160)
void epilogue_kernel(const float* __restrict__ clicked, const float* __restrict__ bg,
                     const float* __restrict__ gamma, const float* __restrict__ beta,
                     float* __restrict__ out)
{
    const int row = blockIdx.x, tid = threadIdx.x;
    const float aw = g_aw[row];
    const float4 c4 = ((const float4*)(clicked + (size_t)row*DMODEL))[tid];
    const uint2 xu  = ((const uint2*)(g_X + (size_t)row*DMODEL))[tid];
    const float4 bg4 = ((const float4*)bg)[tid];
    __nv_bfloat162 x01 = *(const __nv_bfloat162*)&xu.x;
    __nv_bfloat162 x23 = *(const __nv_bfloat162*)&xu.y;
    float xs[4] = { __low2float(x01), __high2float(x01), __low2float(x23), __high2float(x23) };
    float cs[4] = { c4.x, c4.y, c4.z, c4.w };
    float bgs[4] = { bg4.x, bg4.y, bg4.z, bg4.w };
    float ov[4];
    float s = 0.f, sq = 0.f;
    #pragma unroll
    for (int i = 0; i < 4; i++) {
        float z = aw * xs[i] + bgs[i];
        float gate = 1.f / (1.f + __expf(-z));
        float o = gate * (aw * cs[i]) + (1.f - gate) * cs[i];
        ov[i] = o;
        s += o; sq += o*o;
    }
    __shared__ float rs[5], rq[5];
    #pragma unroll
    for (int off = 16; off > 0; off >>= 1) {
        s  += __shfl_xor_sync(0xffffffffu, s, off);
        sq += __shfl_xor_sync(0xffffffffu, sq, off);
    }
    if ((tid & 31) == 0) { rs[tid >> 5] = s; rq[tid >> 5] = sq; }
    __syncthreads();
    float ts = rs[0] + rs[1] + rs[2] + rs[3] + rs[4];
    float tq = rq[0] + rq[1] + rq[2] + rq[3] + rq[4];
    float mu = ts / DMODEL;
    float var = tq / DMODEL - mu*mu;
    float inv = rsqrtf(var + 1e-5f);
    const float4 gm4 = ((const float4*)gamma)[tid];
    const float4 bt4 = ((const float4*)beta)[tid];
    float gms[4] = { gm4.x, gm4.y, gm4.z, gm4.w };
    float bts[4] = { bt4.x, bt4.y, bt4.z, bt4.w };
    float4 o4;
    o4.x = (ov[0] - mu) * inv * gms[0] + bts[0];
    o4.y = (ov[1] - mu) * inv * gms[1] + bts[1];
    o4.z = (ov[2] - mu) * inv * gms[2] + bts[2];
    o4.w = (ov[3] - mu) * inv * gms[3] + bts[3];
    ((float4*)(out + (size_t)row*DMODEL))[tid] = o4;
}

extern "C" void kernel_launch(void* const* d_in, const int* in_sizes, int n_in,
                              void* d_out, int out_size)
{
    const float* clicked_news   = (const float*)d_in[0];
    const float* clicked_topics = (const float*)d_in[1];
    const float* cand_topics    = (const float*)d_in[2];
    const float* Wq = (const float*)d_in[3];
    const float* bq = (const float*)d_in[4];
    const float* Wk = (const float*)d_in[5];
    const float* bk = (const float*)d_in[6];
    const float* Wg = (const float*)d_in[9];
    const float* bg = (const float*)d_in[10];
    const float* ln_gamma = (const float*)d_in[11];
    const float* ln_beta  = (const float*)d_in[12];
    float* out = (float*)d_out;

    cudaFuncSetAttribute(gemm_bf16<true>,  cudaFuncAttributeMaxDynamicSharedMemorySize, GEMM_SMEM);
    cudaFuncSetAttribute(gemm_bf16<false>, cudaFuncAttributeMaxDynamicSharedMemorySize, GEMM_SMEM);
    cudaFuncSetAttribute(attn_kernel, cudaFuncAttributeMaxDynamicSharedMemorySize, ATTN_SMEM);

    __nv_bfloat16 *p_Anb, *p_Atb, *p_Acb, *p_Wkb, *p_Wqb, *p_Wgb, *p_Qbf, *p_Kbf, *p_X;
    cudaGetSymbolAddress((void**)&p_Anb, g_Anb);
    cudaGetSymbolAddress((void**)&p_Atb, g_Atb);
    cudaGetSymbolAddress((void**)&p_Acb, g_Acb);
    cudaGetSymbolAddress((void**)&p_Wkb, g_Wkb);
    cudaGetSymbolAddress((void**)&p_Wqb, g_Wqb);
    cudaGetSymbolAddress((void**)&p_Wgb, g_Wgb);
    cudaGetSymbolAddress((void**)&p_Qbf, g_Qbf);
    cudaGetSymbolAddress((void**)&p_Kbf, g_Kbf);
    cudaGetSymbolAddress((void**)&p_X,   g_X);

    int nsm = 148, occT = 1, occF = 1;
    cudaDeviceGetAttribute(&nsm, cudaDevAttrMultiProcessorCount, 0);
    cudaOccupancyMaxActiveBlocksPerMultiprocessor(&occT, gemm_bf16<true>,  256, GEMM_SMEM);
    cudaOccupancyMaxActiveBlocksPerMultiprocessor(&occF, gemm_bf16<false>, 256, GEMM_SMEM);
    if (occT < 1) occT = 1;
    if (occF < 1) occF = 1;
    const int ntK = NTN * (MROWS_K/128);   // 2000
    const int ntQ = NTN * (MROWS_Q/128);   // 640
    int gT = occT * nsm; if (gT > ntK) gT = ntK;
    int gQ = occT * nsm; if (gQ > ntQ) gQ = ntQ;
    int gF = occF * nsm; if (gF > ntK) gF = ntK;

    // launch order: conv(1), gemmQ(2), gemmK(3), gemmX(4 <- ncu capture), ...
    conv_all_kernel<<<2048, 256>>>(
        clicked_news,   p_Anb, MROWS_K*DMODEL,
        clicked_topics, p_Atb, MROWS_K*256,
        cand_topics,    p_Acb, MROWS_Q*256,
        Wk, p_Wkb, DMODEL*256,
        Wq, p_Wqb, DMODEL*256,
        Wg, p_Wgb, DMODEL*DMODEL);

    gemm_bf16<true><<<gQ, 256, GEMM_SMEM>>>(p_Acb, p_Wqb, bq, p_Qbf, 256, ntQ);
    gemm_bf16<true><<<gT, 256, GEMM_SMEM>>>(p_Atb, p_Wkb, bk, p_Kbf, 256, ntK);
    gemm_bf16<false><<<gF, 256, GEMM_SMEM>>>(p_Anb, p_Wgb, nullptr, p_X, DMODEL, ntK);
    qw_kernel<<<BATCH, 256>>>();
    attn_kernel<<<dim3(NHEADS, BATCH), 128, ATTN_SMEM>>>();
    aggsm_kernel<<<BATCH, 256>>>(out + (size_t)MROWS_K*DMODEL);
    epilogue_kernel<<<MROWS_K, 160>>>(clicked_news, bg, ln_gamma, ln_beta, out);
}

// round 16
// speedup vs baseline: 1.3390x; 1.3346x over previous
#include <cuda_runtime.h>
#include <cuda_bf16.h>
#include <cstdint>
#include <cstddef>
#include <math.h>

#define BATCH  256
#define HCLK   200
#define NCAND  64
#define DMODEL 640
#define NHEADS 10
#define HDIM   64
#define MROWS_K (BATCH*HCLK)
#define MROWS_Q (BATCH*NCAND)

// ---- scratch ----
__device__ __nv_bfloat16 g_Anb[(size_t)MROWS_K*DMODEL];
__device__ __nv_bfloat16 g_Atb[(size_t)MROWS_K*256];
__device__ __nv_bfloat16 g_Acb[(size_t)MROWS_Q*256];
__device__ __nv_bfloat16 g_Wkb[DMODEL*256];
__device__ __nv_bfloat16 g_Wqb[DMODEL*256];
__device__ __nv_bfloat16 g_Wgb[DMODEL*DMODEL];
__device__ __nv_bfloat16 g_Qbf[(size_t)MROWS_Q*DMODEL];
__device__ __nv_bfloat16 g_Kbf[(size_t)MROWS_K*DMODEL];
__device__ __nv_bfloat16 g_X  [(size_t)MROWS_K*DMODEL];
__device__ float         g_qw [MROWS_Q];
__device__ float         g_aggp[(size_t)BATCH*NHEADS*HCLK];
__device__ float         g_aw [MROWS_K];

#define MMA_BF16(d, a, b) \
  asm volatile( \
    "mma.sync.aligned.m16n8k16.row.col.f32.bf16.bf16.f32 " \
    "{%0,%1,%2,%3}, {%4,%5,%6,%7}, {%8,%9}, {%0,%1,%2,%3};\n" \
    : "+f"((d)[0]), "+f"((d)[1]), "+f"((d)[2]), "+f"((d)[3]) \
    : "r"((a)[0]), "r"((a)[1]), "r"((a)[2]), "r"((a)[3]), \
      "r"((b)[0]), "r"((b)[1]))

#define LDSM_X4(r0, r1, r2, r3, saddr) \
  asm volatile("ldmatrix.sync.aligned.m8n8.x4.shared.b16 {%0,%1,%2,%3}, [%4];\n" \
    : "=r"(r0), "=r"(r1), "=r"(r2), "=r"(r3) : "r"(saddr))

#define CP16(dst, src) do { \
    uint32_t _d = (uint32_t)__cvta_generic_to_shared(dst); \
    asm volatile("cp.async.cg.shared.global [%0], [%1], 16;\n" :: "r"(_d), "l"(src)); \
  } while (0)

// ---- single fused fp32 -> bf16 convert for all six tensors ----
__global__ __launch_bounds__(256)
void conv_all_kernel(const float* __restrict__ a0, __nv_bfloat16* __restrict__ o0, int n0,
                     const float* __restrict__ a1, __nv_bfloat16* __restrict__ o1, int n1,
                     const float* __restrict__ a2, __nv_bfloat16* __restrict__ o2, int n2,
                     const float* __restrict__ a3, __nv_bfloat16* __restrict__ o3, int n3,
                     const float* __restrict__ a4, __nv_bfloat16* __restrict__ o4, int n4,
                     const float* __restrict__ a5, __nv_bfloat16* __restrict__ o5, int n5)
{
    const int stride = gridDim.x*256*4;
    const int t0 = (blockIdx.x*256 + threadIdx.x)*4;
    #define CONV_LOOP(a, o, n) \
        for (int i = t0; i < (n); i += stride) { \
            float4 v = *(const float4*)((a) + i); \
            *(__nv_bfloat162*)((o) + i)     = __floats2bfloat162_rn(v.x, v.y); \
            *(__nv_bfloat162*)((o) + i + 2) = __floats2bfloat162_rn(v.z, v.w); \
        }
    CONV_LOOP(a0, o0, n0)
    CONV_LOOP(a1, o1, n1)
    CONV_LOOP(a2, o2, n2)
    CONV_LOOP(a3, o3, n3)
    CONV_LOOP(a4, o4, n4)
    CONV_LOOP(a5, o5, n5)
    #undef CONV_LOOP
}

// ---- bf16 GEMM (2-stage cp.async, ldmatrix, persistent CTAs) ----
#define SST 72
#define GEMM_SMEM (2*256*SST*2)
#define NTN 5
template<bool BIAS>
__global__ __launch_bounds__(256)
void gemm_bf16(const __nv_bfloat16* __restrict__ A, const __nv_bfloat16* __restrict__ W,
               const float* __restrict__ bias, __nv_bfloat16* __restrict__ C,
               int K, int ntiles)
{
    extern __shared__ __nv_bfloat16 sh[];
    const int tid = threadIdx.x;
    const int warp = tid >> 5, lane = tid & 31;
    const int wm = warp & 3, wn = warp >> 2;
    const int g = lane >> 2, tig = lane & 3;

    const int a_r = lane & 15;
    const int a_c = (lane >> 4) << 3;
    const int b_r = ((lane >> 4) << 3) + (lane & 7);
    const int b_c = ((lane >> 3) & 1) << 3;

    const int nk = K / 64;

    for (int t = blockIdx.x; t < ntiles; t += gridDim.x) {
        const int bn0 = (t % NTN)*128;
        const int bm0 = (t / NTN)*128;

        float acc[2][8][4];
        #pragma unroll
        for (int i = 0; i < 2; i++)
          #pragma unroll
          for (int j = 0; j < 8; j++)
            #pragma unroll
            for (int v = 0; v < 4; v++) acc[i][j][v] = 0.f;

        auto issue = [&](int kb, int s) {
            const int k0 = kb * 64;
            __nv_bfloat16* As = sh + s*(256*SST);
            __nv_bfloat16* Bs = As + 128*SST;
            #pragma unroll
            for (int it = 0; it < 4; it++) {
                int idx = tid + it*256;
                int r = idx >> 3, c8 = (idx & 7) << 3;
                CP16(&As[r*SST + c8], &A[(size_t)(bm0 + r)*K + k0 + c8]);
                CP16(&Bs[r*SST + c8], &W[(size_t)(bn0 + r)*K + k0 + c8]);
            }
            asm volatile("cp.async.commit_group;\n");
        };

        issue(0, 0);
        for (int kb = 0; kb < nk; kb++) {
            if (kb + 1 < nk) {
                issue(kb + 1, (kb + 1) & 1);
                asm volatile("cp.async.wait_group 1;\n");
            } else {
                asm volatile("cp.async.wait_group 0;\n");
            }
            __syncthreads();
            const __nv_bfloat16* As = sh + (kb & 1)*(256*SST);
            const __nv_bfloat16* Bs = As + 128*SST;
            uint32_t As0 = (uint32_t)__cvta_generic_to_shared(As);
            uint32_t Bs0 = (uint32_t)__cvta_generic_to_shared(Bs);
            #pragma unroll
            for (int ks = 0; ks < 4; ks++) {
                const int kk = ks*16;
                uint32_t afr[2][4];
                #pragma unroll
                for (int i = 0; i < 2; i++) {
                    uint32_t ad = As0 + ((wm*32 + i*16 + a_r)*SST + kk + a_c)*2;
                    LDSM_X4(afr[i][0], afr[i][1], afr[i][2], afr[i][3], ad);
                }
                uint32_t bfr[4][4];
                #pragma unroll
                for (int j2 = 0; j2 < 4; j2++) {
                    uint32_t bd = Bs0 + ((wn*64 + j2*16 + b_r)*SST + kk + b_c)*2;
                    LDSM_X4(bfr[j2][0], bfr[j2][1], bfr[j2][2], bfr[j2][3], bd);
                }
                #pragma unroll
                for (int i = 0; i < 2; i++)
                  #pragma unroll
                  for (int j2 = 0; j2 < 4; j2++) {
                    MMA_BF16(acc[i][2*j2],   afr[i], (&bfr[j2][0]));
                    MMA_BF16(acc[i][2*j2+1], afr[i], (&bfr[j2][2]));
                  }
            }
            __syncthreads();
        }

        #pragma unroll
        for (int i = 0; i < 2; i++) {
            int row = bm0 + wm*32 + i*16 + g;
            #pragma unroll
            for (int j = 0; j < 8; j++) {
                int col = bn0 + wn*64 + j*8 + 2*tig;
                float b0 = 0.f, b1 = 0.f;
                if (BIAS) { b0 = bias[col]; b1 = bias[col+1]; }
                *(__nv_bfloat162*)(&C[(size_t)row*DMODEL + col]) =
                    __floats2bfloat162_rn(acc[i][j][0] + b0, acc[i][j][1] + b1);
                *(__nv_bfloat162*)(&C[(size_t)(row+8)*DMODEL + col]) =
                    __floats2bfloat162_rn(acc[i][j][2] + b0, acc[i][j][3] + b1);
            }
        }
        __syncthreads();
    }
}

// ---- qw ----
__global__ __launch_bounds__(256)
void qw_kernel()
{
    __shared__ float sv[NCAND], se[NCAND];
    const int b = blockIdx.x, tid = threadIdx.x;
    const int warp = tid >> 5, lane = tid & 31;
    for (int n = warp; n < NCAND; n += 8) {
        const __nv_bfloat16* q = g_Qbf + (size_t)(b*NCAND + n)*DMODEL;
        float ssq = 0.f;
        #pragma unroll
        for (int i = 0; i < 5; i++) {
            int c = (lane + i*32)*4;
            __nv_bfloat162 x0 = *(const __nv_bfloat162*)(q + c);
            __nv_bfloat162 x1 = *(const __nv_bfloat162*)(q + c + 2);
            float a = __low2float(x0), d = __high2float(x0);
            float e = __low2float(x1), f = __high2float(x1);
            ssq += a*a + d*d + e*e + f*f;
        }
        #pragma unroll
        for (int o = 16; o; o >>= 1) ssq += __shfl_xor_sync(0xffffffffu, ssq, o);
        if (lane == 0) sv[n] = sqrtf(ssq);
    }
    __syncthreads();
    if (tid < NCAND) {
        float mx = -1e30f;
        for (int i = 0; i < NCAND; i++) mx = fmaxf(mx, sv[i]);
        se[tid] = __expf(sv[tid] - mx);
    }
    __syncthreads();
    if (tid < NCAND) {
        float s = 0.f;
        for (int i = 0; i < NCAND; i++) s += se[i];
        g_qw[b*NCAND + tid] = se[tid] / s;
    }
}

// ---- attention v2: online softmax, NO scores array. smem 41.2KB -> 5 CTAs/SM ----
#define QSTR 72
#define ATTN_SMEM (64*QSTR*2 + HCLK*QSTR*2 + 4*HCLK*4)   // 41216 B
__global__ __launch_bounds__(128)
void attn_kernel()
{
    extern __shared__ char sm[];
    __nv_bfloat16* Qs = (__nv_bfloat16*)sm;
    __nv_bfloat16* Ks = Qs + 64*QSTR;
    float* wagg = (float*)(sm + 64*QSTR*2 + HCLK*QSTR*2);   // [4][HCLK]

    const int h = blockIdx.x, b = blockIdx.y;
    const int tid = threadIdx.x;
    const int warp = tid >> 5, lane = tid & 31;
    const int g = lane >> 2, tig = lane & 3;

    for (int idx = tid; idx < 64*8; idx += 128) {
        int n = idx >> 3, c = (idx & 7) << 3;
        *(uint4*)(&Qs[n*QSTR + c]) =
            *(const uint4*)(g_Qbf + (size_t)(b*NCAND + n)*DMODEL + h*HDIM + c);
    }
    for (int idx = tid; idx < HCLK*8; idx += 128) {
        int m = idx >> 3, c = (idx & 7) << 3;
        *(uint4*)(&Ks[m*QSTR + c]) =
            *(const uint4*)(g_Kbf + (size_t)(b*HCLK + m)*DMODEL + h*HDIM + c);
    }
    __syncthreads();

    // preload Q fragments: warp rows [16w, 16w+16)
    uint32_t afr[4][4];
    #pragma unroll
    for (int kt = 0; kt < 4; kt++) {
        const __nv_bfloat16* p = &Qs[(warp*16 + g)*QSTR + kt*16 + 2*tig];
        afr[kt][0] = *(const uint32_t*)(p);
        afr[kt][1] = *(const uint32_t*)(p + 8*QSTR);
        afr[kt][2] = *(const uint32_t*)(p + 8);
        afr[kt][3] = *(const uint32_t*)(p + 8*QSTR + 8);
    }
    const float iscale = rsqrtf((float)DMODEL);

    // Pass 1: online (max, den) for rows r0 = 16w+g, r1 = r0+8
    float m0 = -1e30f, l0 = 0.f, m1 = -1e30f, l1 = 0.f;
    for (int nt = 0; nt < 25; nt++) {
        float c4[4] = {0.f, 0.f, 0.f, 0.f};
        #pragma unroll
        for (int kt = 0; kt < 4; kt++) {
            uint32_t bfr[2];
            const __nv_bfloat16* p = &Ks[(nt*8 + g)*QSTR + kt*16 + 2*tig];
            bfr[0] = *(const uint32_t*)(p);
            bfr[1] = *(const uint32_t*)(p + 8);
            MMA_BF16(c4, afr[kt], bfr);
        }
        float s00 = c4[0]*iscale, s01 = c4[1]*iscale;
        float s10 = c4[2]*iscale, s11 = c4[3]*iscale;
        float mn0 = fmaxf(m0, fmaxf(s00, s01));
        l0 = l0*__expf(m0 - mn0) + __expf(s00 - mn0) + __expf(s01 - mn0);
        m0 = mn0;
        float mn1 = fmaxf(m1, fmaxf(s10, s11));
        l1 = l1*__expf(m1 - mn1) + __expf(s10 - mn1) + __expf(s11 - mn1);
        m1 = mn1;
    }
    // merge across the 4 tig lanes of each row group (xor 1, 2)
    #pragma unroll
    for (int o = 1; o <= 2; o <<= 1) {
        float mo = __shfl_xor_sync(0xffffffffu, m0, o);
        float lo = __shfl_xor_sync(0xffffffffu, l0, o);
        float mn = fmaxf(m0, mo);
        l0 = l0*__expf(m0 - mn) + lo*__expf(mo - mn);
        m0 = mn;
        mo = __shfl_xor_sync(0xffffffffu, m1, o);
        lo = __shfl_xor_sync(0xffffffffu, l1, o);
        mn = fmaxf(m1, mo);
        l1 = l1*__expf(m1 - mn) + lo*__expf(mo - mn);
        m1 = mn;
    }
    const float coef0 = g_qw[b*NCAND + warp*16 + g]     / l0;
    const float coef1 = g_qw[b*NCAND + warp*16 + 8 + g] / l1;

    // Pass 2: recompute scores, accumulate coef-weighted exp into column sums
    for (int nt = 0; nt < 25; nt++) {
        float c4[4] = {0.f, 0.f, 0.f, 0.f};
        #pragma unroll
        for (int kt = 0; kt < 4; kt++) {
            uint32_t bfr[2];
            const __nv_bfloat16* p = &Ks[(nt*8 + g)*QSTR + kt*16 + 2*tig];
            bfr[0] = *(const uint32_t*)(p);
            bfr[1] = *(const uint32_t*)(p + 8);
            MMA_BF16(c4, afr[kt], bfr);
        }
        float v0 = coef0*__expf(c4[0]*iscale - m0) + coef1*__expf(c4[2]*iscale - m1);
        float v1 = coef0*__expf(c4[1]*iscale - m0) + coef1*__expf(c4[3]*iscale - m1);
        // sum over the 8 g-groups (rows) of this warp: xor 4, 8, 16
        #pragma unroll
        for (int o = 4; o <= 16; o <<= 1) {
            v0 += __shfl_xor_sync(0xffffffffu, v0, o);
            v1 += __shfl_xor_sync(0xffffffffu, v1, o);
        }
        if (g == 0) {
            wagg[warp*HCLK + nt*8 + 2*tig]     = v0;
            wagg[warp*HCLK + nt*8 + 2*tig + 1] = v1;
        }
    }
    __syncthreads();
    // FIX: strided loop — 128 threads must cover all HCLK=200 columns
    for (int m = tid; m < HCLK; m += 128) {
        g_aggp[((size_t)b*NHEADS + h)*HCLK + m] =
            wagg[m] + wagg[HCLK + m] + wagg[2*HCLK + m] + wagg[3*HCLK + m];
    }
}

// ---- head-reduce + softmax -> aw ----
__global__ __launch_bounds__(256)
void aggsm_kernel(float* __restrict__ out_tail)
{
    __shared__ float sa[HCLK], se2[HCLK];
    const int b = blockIdx.x, t = threadIdx.x;
    if (t < HCLK) {
        float a = 0.f;
        #pragma unroll
        for (int h = 0; h < NHEADS; h++)
            a += g_aggp[((size_t)b*NHEADS + h)*HCLK + t];
        sa[t] = a;
    }
    __syncthreads();
    if (t < HCLK) {
        float mx = -1e30f;
        for (int i = 0; i < HCLK; i++) mx = fmaxf(mx, sa[i]);
        se2[t] = __expf(sa[t] - mx);
    }
    __syncthreads();
    if (t < HCLK) {
        float s = 0.f;
        for (int i = 0; i < HCLK; i++) s += se2[i];
        float aw = se2[t] / s;
        g_aw[b*HCLK + t] = aw;
        out_tail[b*HCLK + t] = aw;
    }
}

// ---- gate + residual + LayerNorm, float4-vectorized ----
__global__ __launch_bounds__(160)
void epilogue_kernel(const float* __restrict__ clicked, const float* __restrict__ bg,
                     const float* __restrict__ gamma, const float* __restrict__ beta,
                     float* __restrict__ out)
{
    const int row = blockIdx.x, tid = threadIdx.x;
    const float aw = g_aw[row];
    const float4 c4 = ((const float4*)(clicked + (size_t)row*DMODEL))[tid];
    const uint2 xu  = ((const uint2*)(g_X + (size_t)row*DMODEL))[tid];
    const float4 bg4 = ((const float4*)bg)[tid];
    __nv_bfloat162 x01 = *(const __nv_bfloat162*)&xu.x;
    __nv_bfloat162 x23 = *(const __nv_bfloat162*)&xu.y;
    float xs[4] = { __low2float(x01), __high2float(x01), __low2float(x23), __high2float(x23) };
    float cs[4] = { c4.x, c4.y, c4.z, c4.w };
    float bgs[4] = { bg4.x, bg4.y, bg4.z, bg4.w };
    float ov[4];
    float s = 0.f, sq = 0.f;
    #pragma unroll
    for (int i = 0; i < 4; i++) {
        float z = aw * xs[i] + bgs[i];
        float gate = 1.f / (1.f + __expf(-z));
        float o = gate * (aw * cs[i]) + (1.f - gate) * cs[i];
        ov[i] = o;
        s += o; sq += o*o;
    }
    __shared__ float rs[5], rq[5];
    #pragma unroll
    for (int off = 16; off > 0; off >>= 1) {
        s  += __shfl_xor_sync(0xffffffffu, s, off);
        sq += __shfl_xor_sync(0xffffffffu, sq, off);
    }
    if ((tid & 31) == 0) { rs[tid >> 5] = s; rq[tid >> 5] = sq; }
    __syncthreads();
    float ts = rs[0] + rs[1] + rs[2] + rs[3] + rs[4];
    float tq = rq[0] + rq[1] + rq[2] + rq[3] + rq[4];
    float mu = ts / DMODEL;
    float var = tq / DMODEL - mu*mu;
    float inv = rsqrtf(var + 1e-5f);
    const float4 gm4 = ((const float4*)gamma)[tid];
    const float4 bt4 = ((const float4*)beta)[tid];
    float gms[4] = { gm4.x, gm4.y, gm4.z, gm4.w };
    float bts[4] = { bt4.x, bt4.y, bt4.z, bt4.w };
    float4 o4;
    o4.x = (ov[0] - mu) * inv * gms[0] + bts[0];
    o4.y = (ov[1] - mu) * inv * gms[1] + bts[1];
    o4.z = (ov[2] - mu) * inv * gms[2] + bts[2];
    o4.w = (ov[3] - mu) * inv * gms[3] + bts[3];
    ((float4*)(out + (size_t)row*DMODEL))[tid] = o4;
}

extern "C" void kernel_launch(void* const* d_in, const int* in_sizes, int n_in,
                              void* d_out, int out_size)
{
    const float* clicked_news   = (const float*)d_in[0];
    const float* clicked_topics = (const float*)d_in[1];
    const float* cand_topics    = (const float*)d_in[2];
    const float* Wq = (const float*)d_in[3];
    const float* bq = (const float*)d_in[4];
    const float* Wk = (const float*)d_in[5];
    const float* bk = (const float*)d_in[6];
    const float* Wg = (const float*)d_in[9];
    const float* bg = (const float*)d_in[10];
    const float* ln_gamma = (const float*)d_in[11];
    const float* ln_beta  = (const float*)d_in[12];
    float* out = (float*)d_out;

    cudaFuncSetAttribute(gemm_bf16<true>,  cudaFuncAttributeMaxDynamicSharedMemorySize, GEMM_SMEM);
    cudaFuncSetAttribute(gemm_bf16<false>, cudaFuncAttributeMaxDynamicSharedMemorySize, GEMM_SMEM);
    cudaFuncSetAttribute(attn_kernel, cudaFuncAttributeMaxDynamicSharedMemorySize, ATTN_SMEM);

    __nv_bfloat16 *p_Anb, *p_Atb, *p_Acb, *p_Wkb, *p_Wqb, *p_Wgb, *p_Qbf, *p_Kbf, *p_X;
    cudaGetSymbolAddress((void**)&p_Anb, g_Anb);
    cudaGetSymbolAddress((void**)&p_Atb, g_Atb);
    cudaGetSymbolAddress((void**)&p_Acb, g_Acb);
    cudaGetSymbolAddress((void**)&p_Wkb, g_Wkb);
    cudaGetSymbolAddress((void**)&p_Wqb, g_Wqb);
    cudaGetSymbolAddress((void**)&p_Wgb, g_Wgb);
    cudaGetSymbolAddress((void**)&p_Qbf, g_Qbf);
    cudaGetSymbolAddress((void**)&p_Kbf, g_Kbf);
    cudaGetSymbolAddress((void**)&p_X,   g_X);

    int nsm = 148, occT = 1, occF = 1;
    cudaDeviceGetAttribute(&nsm, cudaDevAttrMultiProcessorCount, 0);
    cudaOccupancyMaxActiveBlocksPerMultiprocessor(&occT, gemm_bf16<true>,  256, GEMM_SMEM);
    cudaOccupancyMaxActiveBlocksPerMultiprocessor(&occF, gemm_bf16<false>, 256, GEMM_SMEM);
    if (occT < 1) occT = 1;
    if (occF < 1) occF = 1;
    const int ntK = NTN * (MROWS_K/128);   // 2000
    const int ntQ = NTN * (MROWS_Q/128);   // 640
    int gT = occT * nsm; if (gT > ntK) gT = ntK;
    int gQ = occT * nsm; if (gQ > ntQ) gQ = ntQ;
    int gF = occF * nsm; if (gF > ntK) gF = ntK;

    conv_all_kernel<<<2048, 256>>>(
        clicked_news,   p_Anb, MROWS_K*DMODEL,
        clicked_topics, p_Atb, MROWS_K*256,
        cand_topics,    p_Acb, MROWS_Q*256,
        Wk, p_Wkb, DMODEL*256,
        Wq, p_Wqb, DMODEL*256,
        Wg, p_Wgb, DMODEL*DMODEL);

    gemm_bf16<true><<<gQ, 256, GEMM_SMEM>>>(p_Acb, p_Wqb, bq, p_Qbf, 256, ntQ);
    gemm_bf16<true><<<gT, 256, GEMM_SMEM>>>(p_Atb, p_Wkb, bk, p_Kbf, 256, ntK);
    gemm_bf16<false><<<gF, 256, GEMM_SMEM>>>(p_Anb, p_Wgb, nullptr, p_X, DMODEL, ntK);
    qw_kernel<<<BATCH, 256>>>();
    attn_kernel<<<dim3(NHEADS, BATCH), 128, ATTN_SMEM>>>();
    aggsm_kernel<<<BATCH, 256>>>(out + (size_t)MROWS_K*DMODEL);
    epilogue_kernel<<<MROWS_K, 160>>>(clicked_news, bg, ln_gamma, ln_beta, out);
}

// round 17
// speedup vs baseline: 1.3509x; 1.0089x over previous
#include <cuda_runtime.h>
#include <cuda_bf16.h>
#include <cstdint>
#include <cstddef>
#include <math.h>

#define BATCH  256
#define HCLK   200
#define NCAND  64
#define DMODEL 640
#define NHEADS 10
#define HDIM   64
#define MROWS_K (BATCH*HCLK)
#define MROWS_Q (BATCH*NCAND)

// ---- scratch ----
__device__ __nv_bfloat16 g_Anb[(size_t)MROWS_K*DMODEL];
__device__ __nv_bfloat16 g_Atb[(size_t)MROWS_K*256];
__device__ __nv_bfloat16 g_Acb[(size_t)MROWS_Q*256];
__device__ __nv_bfloat16 g_Wkb[DMODEL*256];
__device__ __nv_bfloat16 g_Wqb[DMODEL*256];
__device__ __nv_bfloat16 g_Wgb[DMODEL*DMODEL];
__device__ __nv_bfloat16 g_Qbf[(size_t)MROWS_Q*DMODEL];
__device__ __nv_bfloat16 g_Kbf[(size_t)MROWS_K*DMODEL];
__device__ __nv_bfloat16 g_X  [(size_t)MROWS_K*DMODEL];
__device__ float         g_qw [MROWS_Q];
__device__ float         g_aggp[(size_t)BATCH*NHEADS*HCLK];
__device__ float         g_aw [MROWS_K];

#define MMA_BF16(d, a, b) \
  asm volatile( \
    "mma.sync.aligned.m16n8k16.row.col.f32.bf16.bf16.f32 " \
    "{%0,%1,%2,%3}, {%4,%5,%6,%7}, {%8,%9}, {%0,%1,%2,%3};\n" \
    : "+f"((d)[0]), "+f"((d)[1]), "+f"((d)[2]), "+f"((d)[3]) \
    : "r"((a)[0]), "r"((a)[1]), "r"((a)[2]), "r"((a)[3]), \
      "r"((b)[0]), "r"((b)[1]))

#define LDSM_X4(r0, r1, r2, r3, saddr) \
  asm volatile("ldmatrix.sync.aligned.m8n8.x4.shared.b16 {%0,%1,%2,%3}, [%4];\n" \
    : "=r"(r0), "=r"(r1), "=r"(r2), "=r"(r3) : "r"(saddr))

#define CP16(dst, src) do { \
    uint32_t _d = (uint32_t)__cvta_generic_to_shared(dst); \
    asm volatile("cp.async.cg.shared.global [%0], [%1], 16;\n" :: "r"(_d), "l"(src)); \
  } while (0)

// ---- single fused fp32 -> bf16 convert for all six tensors ----
__global__ __launch_bounds__(256)
void conv_all_kernel(const float* __restrict__ a0, __nv_bfloat16* __restrict__ o0, int n0,
                     const float* __restrict__ a1, __nv_bfloat16* __restrict__ o1, int n1,
                     const float* __restrict__ a2, __nv_bfloat16* __restrict__ o2, int n2,
                     const float* __restrict__ a3, __nv_bfloat16* __restrict__ o3, int n3,
                     const float* __restrict__ a4, __nv_bfloat16* __restrict__ o4, int n4,
                     const float* __restrict__ a5, __nv_bfloat16* __restrict__ o5, int n5)
{
    const int stride = gridDim.x*256*4;
    const int t0 = (blockIdx.x*256 + threadIdx.x)*4;
    #define CONV_LOOP(a, o, n) \
        for (int i = t0; i < (n); i += stride) { \
            float4 v = *(const float4*)((a) + i); \
            *(__nv_bfloat162*)((o) + i)     = __floats2bfloat162_rn(v.x, v.y); \
            *(__nv_bfloat162*)((o) + i + 2) = __floats2bfloat162_rn(v.z, v.w); \
        }
    CONV_LOOP(a0, o0, n0)
    CONV_LOOP(a1, o1, n1)
    CONV_LOOP(a2, o2, n2)
    CONV_LOOP(a3, o3, n3)
    CONV_LOOP(a4, o4, n4)
    CONV_LOOP(a5, o5, n5)
    #undef CONV_LOOP
}

// ---- bf16 GEMM v4: CTA tile 256x128, warp tile 64x64, 3-stage ring ----
#define SST 72
#define TSTAGE (384*SST)                  // A 256 rows + B 128 rows per stage
#define NSTAGE 3
#define GEMM_SMEM (NSTAGE*TSTAGE*2)       // 165888 B
#define NTN 5
template<bool BIAS>
__global__ __launch_bounds__(256)
void gemm_bf16(const __nv_bfloat16* __restrict__ A, const __nv_bfloat16* __restrict__ W,
               const float* __restrict__ bias, __nv_bfloat16* __restrict__ C,
               int K, int ntiles)
{
    extern __shared__ __nv_bfloat16 sh[];
    const int tid = threadIdx.x;
    const int warp = tid >> 5, lane = tid & 31;
    const int wm = warp & 3, wn = warp >> 2;   // 4 x 2 warps -> 256x128
    const int g = lane >> 2, tig = lane & 3;

    const int a_r = lane & 15;
    const int a_c = (lane >> 4) << 3;
    const int b_r = ((lane >> 4) << 3) + (lane & 7);
    const int b_c = ((lane >> 3) & 1) << 3;

    const int nk = K / 64;

    for (int t = blockIdx.x; t < ntiles; t += gridDim.x) {
        const int bn0 = (t % NTN)*128;
        const int bm0 = (t / NTN)*256;

        float acc[4][8][4];
        #pragma unroll
        for (int i = 0; i < 4; i++)
          #pragma unroll
          for (int j = 0; j < 8; j++)
            #pragma unroll
            for (int v = 0; v < 4; v++) acc[i][j][v] = 0.f;

        auto issue = [&](int kb, int s) {
            const int k0 = kb * 64;
            __nv_bfloat16* As = sh + s*TSTAGE;
            __nv_bfloat16* Bs = As + 256*SST;
            #pragma unroll
            for (int it = 0; it < 12; it++) {
                int idx = tid + it*256;           // 0..3071: A 0..2047, B 2048..3071
                if (idx < 2048) {
                    int r = idx >> 3, c8 = (idx & 7) << 3;
                    CP16(&As[r*SST + c8], &A[(size_t)(bm0 + r)*K + k0 + c8]);
                } else {
                    int j = idx - 2048;
                    int r = j >> 3, c8 = (j & 7) << 3;
                    CP16(&Bs[r*SST + c8], &W[(size_t)(bn0 + r)*K + k0 + c8]);
                }
            }
            asm volatile("cp.async.commit_group;\n");
        };

        issue(0, 0);
        issue(1, 1);

        for (int kb = 0; kb < nk; kb++) {
            if (kb + 1 < nk) asm volatile("cp.async.wait_group 1;\n");
            else             asm volatile("cp.async.wait_group 0;\n");
            __syncthreads();
            if (kb + 2 < nk) issue(kb + 2, (kb + 2) % NSTAGE);

            const __nv_bfloat16* As = sh + (kb % NSTAGE)*TSTAGE;
            const __nv_bfloat16* Bs = As + 256*SST;
            uint32_t As0 = (uint32_t)__cvta_generic_to_shared(As);
            uint32_t Bs0 = (uint32_t)__cvta_generic_to_shared(Bs);
            #pragma unroll
            for (int ks = 0; ks < 4; ks++) {
                const int kk = ks*16;
                uint32_t afr[4][4];
                #pragma unroll
                for (int i = 0; i < 4; i++) {
                    uint32_t ad = As0 + ((wm*64 + i*16 + a_r)*SST + kk + a_c)*2;
                    LDSM_X4(afr[i][0], afr[i][1], afr[i][2], afr[i][3], ad);
                }
                uint32_t bfr[4][4];
                #pragma unroll
                for (int j2 = 0; j2 < 4; j2++) {
                    uint32_t bd = Bs0 + ((wn*64 + j2*16 + b_r)*SST + kk + b_c)*2;
                    LDSM_X4(bfr[j2][0], bfr[j2][1], bfr[j2][2], bfr[j2][3], bd);
                }
                #pragma unroll
                for (int i = 0; i < 4; i++)
                  #pragma unroll
                  for (int j2 = 0; j2 < 4; j2++) {
                    MMA_BF16(acc[i][2*j2],   afr[i], (&bfr[j2][0]));
                    MMA_BF16(acc[i][2*j2+1], afr[i], (&bfr[j2][2]));
                  }
            }
        }

        #pragma unroll
        for (int i = 0; i < 4; i++) {
            int row = bm0 + wm*64 + i*16 + g;
            #pragma unroll
            for (int j = 0; j < 8; j++) {
                int col = bn0 + wn*64 + j*8 + 2*tig;
                float b0 = 0.f, b1 = 0.f;
                if (BIAS) { b0 = bias[col]; b1 = bias[col+1]; }
                *(__nv_bfloat162*)(&C[(size_t)row*DMODEL + col]) =
                    __floats2bfloat162_rn(acc[i][j][0] + b0, acc[i][j][1] + b1);
                *(__nv_bfloat162*)(&C[(size_t)(row+8)*DMODEL + col]) =
                    __floats2bfloat162_rn(acc[i][j][2] + b0, acc[i][j][3] + b1);
            }
        }
        __syncthreads();
    }
}

// ---- qw ----
__global__ __launch_bounds__(256)
void qw_kernel()
{
    __shared__ float sv[NCAND], se[NCAND];
    const int b = blockIdx.x, tid = threadIdx.x;
    const int warp = tid >> 5, lane = tid & 31;
    for (int n = warp; n < NCAND; n += 8) {
        const __nv_bfloat16* q = g_Qbf + (size_t)(b*NCAND + n)*DMODEL;
        float ssq = 0.f;
        #pragma unroll
        for (int i = 0; i < 5; i++) {
            int c = (lane + i*32)*4;
            __nv_bfloat162 x0 = *(const __nv_bfloat162*)(q + c);
            __nv_bfloat162 x1 = *(const __nv_bfloat162*)(q + c + 2);
            float a = __low2float(x0), d = __high2float(x0);
            float e = __low2float(x1), f = __high2float(x1);
            ssq += a*a + d*d + e*e + f*f;
        }
        #pragma unroll
        for (int o = 16; o; o >>= 1) ssq += __shfl_xor_sync(0xffffffffu, ssq, o);
        if (lane == 0) sv[n] = sqrtf(ssq);
    }
    __syncthreads();
    if (tid < NCAND) {
        float mx = -1e30f;
        for (int i = 0; i < NCAND; i++) mx = fmaxf(mx, sv[i]);
        se[tid] = __expf(sv[tid] - mx);
    }
    __syncthreads();
    if (tid < NCAND) {
        float s = 0.f;
        for (int i = 0; i < NCAND; i++) s += se[i];
        g_qw[b*NCAND + tid] = se[tid] / s;
    }
}

// ---- attention v2: online softmax, no scores array ----
#define QSTR 72
#define ATTN_SMEM (64*QSTR*2 + HCLK*QSTR*2 + 4*HCLK*4)
__global__ __launch_bounds__(128)
void attn_kernel()
{
    extern __shared__ char sm[];
    __nv_bfloat16* Qs = (__nv_bfloat16*)sm;
    __nv_bfloat16* Ks = Qs + 64*QSTR;
    float* wagg = (float*)(sm + 64*QSTR*2 + HCLK*QSTR*2);

    const int h = blockIdx.x, b = blockIdx.y;
    const int tid = threadIdx.x;
    const int warp = tid >> 5, lane = tid & 31;
    const int g = lane >> 2, tig = lane & 3;

    for (int idx = tid; idx < 64*8; idx += 128) {
        int n = idx >> 3, c = (idx & 7) << 3;
        *(uint4*)(&Qs[n*QSTR + c]) =
            *(const uint4*)(g_Qbf + (size_t)(b*NCAND + n)*DMODEL + h*HDIM + c);
    }
    for (int idx = tid; idx < HCLK*8; idx += 128) {
        int m = idx >> 3, c = (idx & 7) << 3;
        *(uint4*)(&Ks[m*QSTR + c]) =
            *(const uint4*)(g_Kbf + (size_t)(b*HCLK + m)*DMODEL + h*HDIM + c);
    }
    __syncthreads();

    uint32_t afr[4][4];
    #pragma unroll
    for (int kt = 0; kt < 4; kt++) {
        const __nv_bfloat16* p = &Qs[(warp*16 + g)*QSTR + kt*16 + 2*tig];
        afr[kt][0] = *(const uint32_t*)(p);
        afr[kt][1] = *(const uint32_t*)(p + 8*QSTR);
        afr[kt][2] = *(const uint32_t*)(p + 8);
        afr[kt][3] = *(const uint32_t*)(p + 8*QSTR + 8);
    }
    const float iscale = rsqrtf((float)DMODEL);

    float m0 = -1e30f, l0 = 0.f, m1 = -1e30f, l1 = 0.f;
    for (int nt = 0; nt < 25; nt++) {
        float c4[4] = {0.f, 0.f, 0.f, 0.f};
        #pragma unroll
        for (int kt = 0; kt < 4; kt++) {
            uint32_t bfr[2];
            const __nv_bfloat16* p = &Ks[(nt*8 + g)*QSTR + kt*16 + 2*tig];
            bfr[0] = *(const uint32_t*)(p);
            bfr[1] = *(const uint32_t*)(p + 8);
            MMA_BF16(c4, afr[kt], bfr);
        }
        float s00 = c4[0]*iscale, s01 = c4[1]*iscale;
        float s10 = c4[2]*iscale, s11 = c4[3]*iscale;
        float mn0 = fmaxf(m0, fmaxf(s00, s01));
        l0 = l0*__expf(m0 - mn0) + __expf(s00 - mn0) + __expf(s01 - mn0);
        m0 = mn0;
        float mn1 = fmaxf(m1, fmaxf(s10, s11));
        l1 = l1*__expf(m1 - mn1) + __expf(s10 - mn1) + __expf(s11 - mn1);
        m1 = mn1;
    }
    #pragma unroll
    for (int o = 1; o <= 2; o <<= 1) {
        float mo = __shfl_xor_sync(0xffffffffu, m0, o);
        float lo = __shfl_xor_sync(0xffffffffu, l0, o);
        float mn = fmaxf(m0, mo);
        l0 = l0*__expf(m0 - mn) + lo*__expf(mo - mn);
        m0 = mn;
        mo = __shfl_xor_sync(0xffffffffu, m1, o);
        lo = __shfl_xor_sync(0xffffffffu, l1, o);
        mn = fmaxf(m1, mo);
        l1 = l1*__expf(m1 - mn) + lo*__expf(mo - mn);
        m1 = mn;
    }
    const float coef0 = g_qw[b*NCAND + warp*16 + g]     / l0;
    const float coef1 = g_qw[b*NCAND + warp*16 + 8 + g] / l1;

    for (int nt = 0; nt < 25; nt++) {
        float c4[4] = {0.f, 0.f, 0.f, 0.f};
        #pragma unroll
        for (int kt = 0; kt < 4; kt++) {
            uint32_t bfr[2];
            const __nv_bfloat16* p = &Ks[(nt*8 + g)*QSTR + kt*16 + 2*tig];
            bfr[0] = *(const uint32_t*)(p);
            bfr[1] = *(const uint32_t*)(p + 8);
            MMA_BF16(c4, afr[kt], bfr);
        }
        float v0 = coef0*__expf(c4[0]*iscale - m0) + coef1*__expf(c4[2]*iscale - m1);
        float v1 = coef0*__expf(c4[1]*iscale - m0) + coef1*__expf(c4[3]*iscale - m1);
        #pragma unroll
        for (int o = 4; o <= 16; o <<= 1) {
            v0 += __shfl_xor_sync(0xffffffffu, v0, o);
            v1 += __shfl_xor_sync(0xffffffffu, v1, o);
        }
        if (g == 0) {
            wagg[warp*HCLK + nt*8 + 2*tig]     = v0;
            wagg[warp*HCLK + nt*8 + 2*tig + 1] = v1;
        }
    }
    __syncthreads();
    for (int m = tid; m < HCLK; m += 128) {
        g_aggp[((size_t)b*NHEADS + h)*HCLK + m] =
            wagg[m] + wagg[HCLK + m] + wagg[2*HCLK + m] + wagg[3*HCLK + m];
    }
}

// ---- head-reduce + softmax -> aw ----
__global__ __launch_bounds__(256)
void aggsm_kernel(float* __restrict__ out_tail)
{
    __shared__ float sa[HCLK], se2[HCLK];
    const int b = blockIdx.x, t = threadIdx.x;
    if (t < HCLK) {
        float a = 0.f;
        #pragma unroll
        for (int h = 0; h < NHEADS; h++)
            a += g_aggp[((size_t)b*NHEADS + h)*HCLK + t];
        sa[t] = a;
    }
    __syncthreads();
    if (t < HCLK) {
        float mx = -1e30f;
        for (int i = 0; i < HCLK; i++) mx = fmaxf(mx, sa[i]);
        se2[t] = __expf(sa[t] - mx);
    }
    __syncthreads();
    if (t < HCLK) {
        float s = 0.f;
        for (int i = 0; i < HCLK; i++) s += se2[i];
        float aw = se2[t] / s;
        g_aw[b*HCLK + t] = aw;
        out_tail[b*HCLK + t] = aw;
    }
}

// ---- gate + residual + LayerNorm, float4-vectorized ----
__global__ __launch_bounds__(160)
void epilogue_kernel(const float* __restrict__ clicked, const float* __restrict__ bg,
                     const float* __restrict__ gamma, const float* __restrict__ beta,
                     float* __restrict__ out)
{
    const int row = blockIdx.x, tid = threadIdx.x;
    const float aw = g_aw[row];
    const float4 c4 = ((const float4*)(clicked + (size_t)row*DMODEL))[tid];
    const uint2 xu  = ((const uint2*)(g_X + (size_t)row*DMODEL))[tid];
    const float4 bg4 = ((const float4*)bg)[tid];
    __nv_bfloat162 x01 = *(const __nv_bfloat162*)&xu.x;
    __nv_bfloat162 x23 = *(const __nv_bfloat162*)&xu.y;
    float xs[4] = { __low2float(x01), __high2float(x01), __low2float(x23), __high2float(x23) };
    float cs[4] = { c4.x, c4.y, c4.z, c4.w };
    float bgs[4] = { bg4.x, bg4.y, bg4.z, bg4.w };
    float ov[4];
    float s = 0.f, sq = 0.f;
    #pragma unroll
    for (int i = 0; i < 4; i++) {
        float z = aw * xs[i] + bgs[i];
        float gate = 1.f / (1.f + __expf(-z));
        float o = gate * (aw * cs[i]) + (1.f - gate) * cs[i];
        ov[i] = o;
        s += o; sq += o*o;
    }
    __shared__ float rs[5], rq[5];
    #pragma unroll
    for (int off = 16; off > 0; off >>= 1) {
        s  += __shfl_xor_sync(0xffffffffu, s, off);
        sq += __shfl_xor_sync(0xffffffffu, sq, off);
    }
    if ((tid & 31) == 0) { rs[tid >> 5] = s; rq[tid >> 5] = sq; }
    __syncthreads();
    float ts = rs[0] + rs[1] + rs[2] + rs[3] + rs[4];
    float tq = rq[0] + rq[1] + rq[2] + rq[3] + rq[4];
    float mu = ts / DMODEL;
    float var = tq / DMODEL - mu*mu;
    float inv = rsqrtf(var + 1e-5f);
    const float4 gm4 = ((const float4*)gamma)[tid];
    const float4 bt4 = ((const float4*)beta)[tid];
    float gms[4] = { gm4.x, gm4.y, gm4.z, gm4.w };
    float bts[4] = { bt4.x, bt4.y, bt4.z, bt4.w };
    float4 o4;
    o4.x = (ov[0] - mu) * inv * gms[0] + bts[0];
    o4.y = (ov[1] - mu) * inv * gms[1] + bts[1];
    o4.z = (ov[2] - mu) * inv * gms[2] + bts[2];
    o4.w = (ov[3] - mu) * inv * gms[3] + bts[3];
    ((float4*)(out + (size_t)row*DMODEL))[tid] = o4;
}

extern "C" void kernel_launch(void* const* d_in, const int* in_sizes, int n_in,
                              void* d_out, int out_size)
{
    const float* clicked_news   = (const float*)d_in[0];
    const float* clicked_topics = (const float*)d_in[1];
    const float* cand_topics    = (const float*)d_in[2];
    const float* Wq = (const float*)d_in[3];
    const float* bq = (const float*)d_in[4];
    const float* Wk = (const float*)d_in[5];
    const float* bk = (const float*)d_in[6];
    const float* Wg = (const float*)d_in[9];
    const float* bg = (const float*)d_in[10];
    const float* ln_gamma = (const float*)d_in[11];
    const float* ln_beta  = (const float*)d_in[12];
    float* out = (float*)d_out;

    cudaFuncSetAttribute(gemm_bf16<true>,  cudaFuncAttributeMaxDynamicSharedMemorySize, GEMM_SMEM);
    cudaFuncSetAttribute(gemm_bf16<false>, cudaFuncAttributeMaxDynamicSharedMemorySize, GEMM_SMEM);
    cudaFuncSetAttribute(attn_kernel, cudaFuncAttributeMaxDynamicSharedMemorySize, ATTN_SMEM);

    __nv_bfloat16 *p_Anb, *p_Atb, *p_Acb, *p_Wkb, *p_Wqb, *p_Wgb, *p_Qbf, *p_Kbf, *p_X;
    cudaGetSymbolAddress((void**)&p_Anb, g_Anb);
    cudaGetSymbolAddress((void**)&p_Atb, g_Atb);
    cudaGetSymbolAddress((void**)&p_Acb, g_Acb);
    cudaGetSymbolAddress((void**)&p_Wkb, g_Wkb);
    cudaGetSymbolAddress((void**)&p_Wqb, g_Wqb);
    cudaGetSymbolAddress((void**)&p_Wgb, g_Wgb);
    cudaGetSymbolAddress((void**)&p_Qbf, g_Qbf);
    cudaGetSymbolAddress((void**)&p_Kbf, g_Kbf);
    cudaGetSymbolAddress((void**)&p_X,   g_X);

    int nsm = 148, occT = 1, occF = 1;
    cudaDeviceGetAttribute(&nsm, cudaDevAttrMultiProcessorCount, 0);
    cudaOccupancyMaxActiveBlocksPerMultiprocessor(&occT, gemm_bf16<true>,  256, GEMM_SMEM);
    cudaOccupancyMaxActiveBlocksPerMultiprocessor(&occF, gemm_bf16<false>, 256, GEMM_SMEM);
    if (occT < 1) occT = 1;
    if (occF < 1) occF = 1;
    const int ntK = NTN * (MROWS_K/256);   // 1000
    const int ntQ = NTN * (MROWS_Q/256);   // 320
    int gT = occT * nsm; if (gT > ntK) gT = ntK;
    int gQ = occT * nsm; if (gQ > ntQ) gQ = ntQ;
    int gF = occF * nsm; if (gF > ntK) gF = ntK;

    conv_all_kernel<<<2048, 256>>>(
        clicked_news,   p_Anb, MROWS_K*DMODEL,
        clicked_topics, p_Atb, MROWS_K*256,
        cand_topics,    p_Acb, MROWS_Q*256,
        Wk, p_Wkb, DMODEL*256,
        Wq, p_Wqb, DMODEL*256,
        Wg, p_Wgb, DMODEL*DMODEL);

    gemm_bf16<true><<<gQ, 256, GEMM_SMEM>>>(p_Acb, p_Wqb, bq, p_Qbf, 256, ntQ);
    gemm_bf16<true><<<gT, 256, GEMM_SMEM>>>(p_Atb, p_Wkb, bk, p_Kbf, 256, ntK);
    gemm_bf16<false><<<gF, 256, GEMM_SMEM>>>(p_Anb, p_Wgb, nullptr, p_X, DMODEL, ntK);
    qw_kernel<<<BATCH, 256>>>();
    attn_kernel<<<dim3(NHEADS, BATCH), 128, ATTN_SMEM>>>();
    aggsm_kernel<<<BATCH, 256>>>(out + (size_t)MROWS_K*DMODEL);
    epilogue_kernel<<<MROWS_K, 160>>>(clicked_news, bg, ln_gamma, ln_beta, out);
}